// round 9
// baseline (speedup 1.0000x reference)
#include <cuda_runtime.h>
#include <cuda_bf16.h>
#include <math.h>
#include <stdint.h>

// Problem constants
#define Bn   1024
#define Tn   512
#define Dn   64
#define Hn   256
#define G4   1024
#define MIDn 64
#define An   3

// CTA = 128 rows x 64 gate-cols. K=320: x = 2 chunks k32 (k 256..319) computed
// before the barrier; h = 8 chunks k32 (k 0..255) in a 4-buffer ring.
// A chunk buffer: 3 planes x 64 smem-rows x 128B (two m-halves per row), XOR swizzle.
#define ABUF   24576                    // per A ring buffer
#define NBUF   4
#define B_OFF  (NBUF*ABUF)              // 98304
#define BPITCH 640
#define SMEM_TOT (B_OFF + 3*64*BPITCH)  // 98304 + 122880 = 221184
#define HS_OFF (2*ABUF)                 // epilogue staging in ring slot 2

// ---------------- device scratch (static, no allocation) ----------------
__device__ __nv_bfloat16 g_W[3][G4][320];          // [plane][gatecol][k] k0..255=h, 256..319=x
__device__ __nv_bfloat16 g_xT[3][Tn][Bn][Dn];      // split x, t-major
__device__ __nv_bfloat16 g_h[2][3][Bn][Hn];        // ping-pong split h
__device__ float g_br[G4];
__device__ float g_hfull[Bn*Hn];
__device__ float g_a1[Bn*MIDn];
__device__ float g_v1[Bn*MIDn];
__device__ int   g_bar[8];

// ---------------- helpers ----------------
__device__ __forceinline__ void split3(float v, __nv_bfloat16& b1,
                                       __nv_bfloat16& b2, __nv_bfloat16& b3) {
    b1 = __float2bfloat16(v);
    float r = v - __bfloat162float(b1);
    b2 = __float2bfloat16(r);
    float r2 = r - __bfloat162float(b2);
    b3 = __float2bfloat16(r2);
}

__device__ __forceinline__ uint32_t smem_u32(const void* p) {
    uint32_t a;
    asm("{ .reg .u64 t; cvta.to.shared.u64 t, %1; cvt.u32.u64 %0, t; }" : "=r"(a) : "l"(p));
    return a;
}

__device__ __forceinline__ void cp16(uint32_t dst, const void* src) {
    asm volatile("cp.async.cg.shared.global [%0], [%1], 16;" :: "r"(dst), "l"(src) : "memory");
}
__device__ __forceinline__ void cp_commit() {
    asm volatile("cp.async.commit_group;" ::: "memory");
}

#define LDSM4(R, addr) \
    asm volatile("ldmatrix.sync.aligned.m8n8.x4.shared.b16 {%0,%1,%2,%3}, [%4];" \
        : "=r"((R)[0]), "=r"((R)[1]), "=r"((R)[2]), "=r"((R)[3]) : "r"(addr))

__device__ __forceinline__ void mma_bf16(float c[4], const uint32_t a[4],
                                         uint32_t b0, uint32_t b1) {
    asm volatile(
        "mma.sync.aligned.m16n8k16.row.col.f32.bf16.bf16.f32 "
        "{%0,%1,%2,%3}, {%4,%5,%6,%7}, {%8,%9}, {%0,%1,%2,%3};"
        : "+f"(c[0]), "+f"(c[1]), "+f"(c[2]), "+f"(c[3])
        : "r"(a[0]), "r"(a[1]), "r"(a[2]), "r"(a[3]), "r"(b0), "r"(b1));
}

// A-chunk smem offset for logical (plane, m 0..127, byte off 0..63 within k32 row)
__device__ __forceinline__ uint32_t a_off(int p, int m, int kb) {
    uint32_t inrow = ((uint32_t)(m >> 6) << 6) + (uint32_t)kb;
    inrow ^= (uint32_t)((m & 7) << 4);
    return (uint32_t)p * 8192 + (uint32_t)(m & 63) * 128 + inrow;
}

// ---------------- prep kernels ----------------
// k-space: k 0..255 = h units (Wc rows 64+k), k 256..319 = x dims (Wc rows k-256)
__global__ void wsplit_kernel(const float* __restrict__ Wc, const float* __restrict__ bc) {
    int idx = blockIdx.x * blockDim.x + threadIdx.x;
    if (idx < G4 * 320) {
        int k = idx % 320;
        int gcol = idx / 320;
        int u = gcol >> 2, g = gcol & 3;
        int r = (k < 256) ? (64 + k) : (k - 256);
        float w = Wc[r * G4 + g * Hn + u];
        __nv_bfloat16 s[3];
        split3(w, s[0], s[1], s[2]);
#pragma unroll
        for (int p = 0; p < 3; p++) g_W[p][gcol][k] = s[p];
    }
    if (idx < G4) {
        int u = idx >> 2, g = idx & 3;
        g_br[idx] = bc[g * Hn + u];
    }
}

__global__ void xsplit_kernel(const float* __restrict__ x) {
    int idx = blockIdx.x * blockDim.x + threadIdx.x;
    int d = idx & 63;
    int tt = (idx >> 6) & 511;
    int b = idx >> 15;
    if (b >= Bn) return;
    float v = x[((size_t)b * Tn + tt) * Dn + d];
    __nv_bfloat16 s[3];
    split3(v, s[0], s[1], s[2]);
#pragma unroll
    for (int p = 0; p < 3; p++) g_xT[p][tt][b][d] = s[p];
}

__global__ void init_kernel() {
    int idx = blockIdx.x * blockDim.x + threadIdx.x;
    if (idx < 3 * Bn * Hn / 2)
        ((unsigned*)g_h[0])[idx] = 0u;
    if (idx < 8) g_bar[idx] = 0;
}

// ---------------- persistent step kernel ----------------
// grid (8, 16): bi = batch slice (128 rows), ci = 16 hidden units (64 gate cols)
__global__ __launch_bounds__(256)
void step_kernel() {
    extern __shared__ char dsm[];
    const uint32_t sbase = smem_u32(dsm);

    const int tid  = threadIdx.x;
    const int lane = tid & 31;
    const int warp = tid >> 5;
    const int wm = warp & 3;
    const int wn = warp >> 2;
    const int bi = blockIdx.x;
    const int ci = blockIdx.y;
    const int row0 = bi * 128;

    // resident B (weights, K=320): 3 planes x 64 cols x 640B, XOR-swizzled
#pragma unroll
    for (int i = 0; i < 30; i++) {
        int flat = i * 256 + tid;                 // < 7680
        int q = flat % 40;
        int n = (flat / 40) & 63;
        int p = flat / 2560;
        uint32_t off = (uint32_t)(q * 16) ^ (uint32_t)((n & 7) << 4);
        cp16(sbase + B_OFF + (uint32_t)(p * 64 + n) * BPITCH + off,
             (const char*)&g_W[p][ci * 64 + n][q * 8]);
    }
    cp_commit();

    float cold[8], nold[8];
#pragma unroll
    for (int q = 0; q < 8; q++) { cold[q] = 0.0f; nold[q] = 1.0f; }

    const int mrow = lane & 15;
    const int kAo  = (lane >> 4) << 3;
    const int nBo  = ((lane >> 4) << 3) + (lane & 7);
    const int kBo  = ((lane >> 3) & 1) << 3;
    const bool odd = lane & 1;
    const int jh = (lane >> 1) & 1;

    float cm[2][4][4], cl[2][4][4], cx[2][4][4];

    // one k=32 chunk: 2 k16 steps, 6-product bf16x6
    auto do_chunk32 = [&](uint32_t abase, uint32_t bko) {
#pragma unroll
        for (int ks = 0; ks < 2; ks++) {
            uint32_t a[3][2][4], b[3][2][4];
#pragma unroll
            for (int p = 0; p < 3; p++) {
#pragma unroll
                for (int mi = 0; mi < 2; mi++) {
                    int arow = wm * 32 + mi * 16 + mrow;
                    LDSM4(a[p][mi], abase + a_off(p, arow, (ks * 16 + kAo) * 2));
                }
#pragma unroll
                for (int pr = 0; pr < 2; pr++) {
                    int brow = wn * 32 + pr * 16 + nBo;
                    uint32_t off = (bko + (uint32_t)((ks * 16 + kBo) * 2)) ^ (uint32_t)((brow & 7) << 4);
                    LDSM4(b[p][pr], sbase + B_OFF + (uint32_t)(p * 64 + brow) * BPITCH + off);
                }
            }
#pragma unroll
            for (int mi = 0; mi < 2; mi++)
#pragma unroll
                for (int ni = 0; ni < 4; ni++) {
                    const int pr = ni >> 1, o = (ni & 1) * 2;
                    mma_bf16(cm[mi][ni], a[0][mi], b[0][pr][o], b[0][pr][o+1]); // hi*hi
                    mma_bf16(cl[mi][ni], a[0][mi], b[1][pr][o], b[1][pr][o+1]); // hi*mid
                    mma_bf16(cl[mi][ni], a[1][mi], b[0][pr][o], b[0][pr][o+1]); // mid*hi
                    mma_bf16(cl[mi][ni], a[0][mi], b[2][pr][o], b[2][pr][o+1]); // hi*lo
                    mma_bf16(cl[mi][ni], a[1][mi], b[1][pr][o], b[1][pr][o+1]); // mid*mid
                    mma_bf16(cl[mi][ni], a[2][mi], b[0][pr][o], b[0][pr][o+1]); // lo*hi
                }
        }
    };

    // x prefetch for step t into ring bufs 0,1 (one commit group)
    auto issue_x = [&](int t) {
#pragma unroll
        for (int i = 0; i < 12; i++) {
            int flat = i * 256 + tid;             // < 3072 = 2 x 1536
            int c  = flat / 1536;
            int f2 = flat - c * 1536;
            int q = f2 & 3;
            int m = (f2 >> 2) & 127;
            int p = f2 >> 9;
            cp16(sbase + (uint32_t)c * ABUF + a_off(p, m, q * 16),
                 (const char*)&g_xT[p][t][row0 + m][c * 32 + q * 8]);
        }
        cp_commit();
    };

    issue_x(0);   // t=0 x prefetch (waits also cover the B group)

    for (int t = 0; t < Tn; t++) {
        const int hbuf = t & 1;

        // h-chunk producer: chunk ch (k = ch*32..) -> ring buf ch&3
        auto issue_h = [&](int ch) {
            const uint32_t abase = sbase + (uint32_t)(ch & 3) * ABUF;
#pragma unroll
            for (int i = 0; i < 6; i++) {
                int flat = i * 256 + tid;         // < 1536
                int q = flat & 3;
                int m = (flat >> 2) & 127;
                int p = flat >> 9;
                cp16(abase + a_off(p, m, q * 16),
                     (const char*)&g_h[hbuf][p][row0 + m][ch * 32 + q * 8]);
            }
            cp_commit();
        };

#pragma unroll
        for (int mi = 0; mi < 2; mi++)
#pragma unroll
            for (int ni = 0; ni < 4; ni++)
#pragma unroll
                for (int q = 0; q < 4; q++) { cm[mi][ni][q] = 0.0f; cl[mi][ni][q] = 0.0f; }

        // ---- x phase (prefetched last step): compute BEFORE barrier ----
        asm volatile("cp.async.wait_group 0;" ::: "memory");
        __syncthreads();
        do_chunk32(sbase + 0 * ABUF, 512u);       // k 256..287
        do_chunk32(sbase + 1 * ABUF, 576u);       // k 288..319

        // collapse x part + bias into cx, reset cm/cl
#pragma unroll
        for (int mi = 0; mi < 2; mi++)
#pragma unroll
            for (int ni = 0; ni < 4; ni++) {
                int col = ci * 64 + wn * 32 + ni * 8 + (lane & 3) * 2;
                float b0 = g_br[col], b1 = g_br[col + 1];
                cx[mi][ni][0] = cm[mi][ni][0] + cl[mi][ni][0] + b0;
                cx[mi][ni][1] = cm[mi][ni][1] + cl[mi][ni][1] + b1;
                cx[mi][ni][2] = cm[mi][ni][2] + cl[mi][ni][2] + b0;
                cx[mi][ni][3] = cm[mi][ni][3] + cl[mi][ni][3] + b1;
#pragma unroll
                for (int q = 0; q < 4; q++) { cm[mi][ni][q] = 0.0f; cl[mi][ni][q] = 0.0f; }
            }

        // ---- barrier: wait for h(t) from all 16 CTAs of this bi group ----
        if (t > 0 && tid == 0) {
            const int target = 16 * t;
            while (((volatile int*)g_bar)[bi] < target) { }
            __threadfence();
        }
        __syncthreads();   // also: all warps past x LDSM -> ring bufs reusable

        // ---- h phase: 8 chunks k=32, 4-buffer ring, one sync per chunk ----
        issue_h(0); issue_h(1); issue_h(2);

#pragma unroll 1
        for (int ch = 0; ch < 8; ch++) {
            if (ch <= 5)      asm volatile("cp.async.wait_group 2;" ::: "memory");
            else if (ch == 6) asm volatile("cp.async.wait_group 1;" ::: "memory");
            else              asm volatile("cp.async.wait_group 0;" ::: "memory");
            __syncthreads();
            if (ch + 3 < 8) issue_h(ch + 3);      // refill buf (ch-1)&3: safe post-sync
            do_chunk32(sbase + (uint32_t)(ch & 3) * ABUF, (uint32_t)(ch * 64));
        }

        const bool last = (t == Tn - 1);
        if (!last) issue_x(t + 1);                // hide x load behind epilogue+barrier

        // ---- epilogue ----
        __syncthreads();                          // all LDSM done; Hs slot (buf2) free
        __nv_bfloat16* Hs = (__nv_bfloat16*)(dsm + HS_OFF);  // [3][128][16]

#pragma unroll
        for (int mi = 0; mi < 2; mi++)
#pragma unroll
            for (int ni = 0; ni < 4; ni++) {
                float q0 = (cm[mi][ni][0] + cl[mi][ni][0]) + cx[mi][ni][0];
                float q1 = (cm[mi][ni][1] + cl[mi][ni][1]) + cx[mi][ni][1];
                float q2 = (cm[mi][ni][2] + cl[mi][ni][2]) + cx[mi][ni][2];
                float q3 = (cm[mi][ni][3] + cl[mi][ni][3]) + cx[mi][ni][3];
                float s0 = __shfl_xor_sync(0xFFFFFFFFu, q0, 1);
                float s1 = __shfl_xor_sync(0xFFFFFFFFu, q1, 1);
                float s2 = __shfl_xor_sync(0xFFFFFFFFu, q2, 1);
                float s3 = __shfl_xor_sync(0xFFFFFFFFu, q3, 1);

                float gi = odd ? s2 : q0;
                float gf = odd ? s3 : q1;
                float go = odd ? q2 : s0;
                float gz = odd ? q3 : s1;

                const int row = wm * 32 + mi * 16 + (lane >> 2) + (odd ? 8 : 0);
                const int ul  = wn * 8 + ni * 2 + jh;
                const int qi  = mi * 4 + ni;

                gi = fminf(fmaxf(gi, -5.0f), 5.0f);
                gf = fminf(fmaxf(gf, -5.0f), 5.0f);
                float iv = __expf(gi);
                float fv = __expf(gf);

                float cv = fv * cold[qi] + iv * (1.0f - 2.0f / (__expf(2.0f * gz) + 1.0f));
                cv = fminf(fmaxf(cv, -1e6f), 1e6f);
                float nv = fv * nold[qi] + iv;
                nv = fminf(fmaxf(nv, 1e-6f), 1e6f);
                cold[qi] = cv;
                nold[qi] = nv;

                float ov = 1.0f / (1.0f + __expf(-go));
                float hv = ov * (cv / nv);
                if (!isfinite(hv)) hv = 0.0f;

                __nv_bfloat16 h1, h2, h3;
                split3(hv, h1, h2, h3);
                Hs[(0 * 128 + row) * 16 + ul] = h1;
                Hs[(1 * 128 + row) * 16 + ul] = h2;
                Hs[(2 * 128 + row) * 16 + ul] = h3;
                if (last) g_hfull[(row0 + row) * Hn + ci * 16 + ul] = hv;
            }
        __syncthreads();

        if (!last) {
            const int nbuf = hbuf ^ 1;
#pragma unroll
            for (int i = 0; i < 3; i++) {
                int flat = i * 256 + tid;
                int q = flat & 1;
                int m = (flat >> 1) & 127;
                int p = flat >> 8;
                uint4 v = *(const uint4*)&Hs[(p * 128 + m) * 16 + q * 8];
                *(uint4*)&g_h[nbuf][p][row0 + m][ci * 16 + q * 8] = v;
            }
            __threadfence();
            __syncthreads();                      // Hs reads done; h visible
            if (tid == 0) atomicAdd(&g_bar[bi], 1);
        }
    }
}

// ---------------- heads ----------------
__global__ void heads1_kernel(const float* __restrict__ Wa1, const float* __restrict__ ba1,
                              const float* __restrict__ Wv1, const float* __restrict__ bv1) {
    int idx = blockIdx.x * blockDim.x + threadIdx.x;
    if (idx >= Bn * 128) return;
    int b = idx >> 7;
    int j = idx & 127;
    const float* hrow = g_hfull + b * Hn;
    if (j < MIDn) {
        float s = ba1[j];
#pragma unroll 8
        for (int k = 0; k < Hn; k++) s = fmaf(hrow[k], Wa1[k * MIDn + j], s);
        g_a1[b * MIDn + j] = fmaxf(s, 0.0f);
    } else {
        int jj = j - MIDn;
        float s = bv1[jj];
#pragma unroll 8
        for (int k = 0; k < Hn; k++) s = fmaf(hrow[k], Wv1[k * MIDn + jj], s);
        g_v1[b * MIDn + jj] = fmaxf(s, 0.0f);
    }
}

__global__ void heads2_kernel(const float* __restrict__ Wa2, const float* __restrict__ ba2,
                              const float* __restrict__ Wv2, const float* __restrict__ bv2,
                              float* __restrict__ out) {
    int b = blockIdx.x * blockDim.x + threadIdx.x;
    if (b >= Bn) return;
    float l0 = ba2[0], l1 = ba2[1], l2 = ba2[2];
#pragma unroll 8
    for (int m = 0; m < MIDn; m++) {
        float a = g_a1[b * MIDn + m];
        l0 = fmaf(a, Wa2[m * An + 0], l0);
        l1 = fmaf(a, Wa2[m * An + 1], l1);
        l2 = fmaf(a, Wa2[m * An + 2], l2);
    }
    float mx = fmaxf(l0, fmaxf(l1, l2));
    float e0 = expf(l0 - mx), e1 = expf(l1 - mx), e2 = expf(l2 - mx);
    float s = e0 + e1 + e2;
    out[b * An + 0] = e0 / s;
    out[b * An + 1] = e1 / s;
    out[b * An + 2] = e2 / s;

    float v = bv2[0];
#pragma unroll 8
    for (int m = 0; m < MIDn; m++) v = fmaf(g_v1[b * MIDn + m], Wv2[m], v);
    out[Bn * An + b] = v;
}

// ---------------- launch ----------------
extern "C" void kernel_launch(void* const* d_in, const int* in_sizes, int n_in,
                              void* d_out, int out_size) {
    const float* x   = (const float*)d_in[0];
    const float* Wc  = (const float*)d_in[1];
    const float* bc  = (const float*)d_in[2];
    const float* Wa1 = (const float*)d_in[3];
    const float* ba1 = (const float*)d_in[4];
    const float* Wa2 = (const float*)d_in[5];
    const float* ba2 = (const float*)d_in[6];
    const float* Wv1 = (const float*)d_in[7];
    const float* bv1 = (const float*)d_in[8];
    const float* Wv2 = (const float*)d_in[9];
    const float* bv2 = (const float*)d_in[10];
    float* out = (float*)d_out;

    cudaFuncSetAttribute(step_kernel, cudaFuncAttributeMaxDynamicSharedMemorySize, SMEM_TOT);

    wsplit_kernel<<<(G4 * 320 + 255) / 256, 256>>>(Wc, bc);
    xsplit_kernel<<<(Bn * Tn * Dn + 255) / 256, 256>>>(x);
    init_kernel<<<(3 * Bn * Hn / 2 + 255) / 256, 256>>>();

    step_kernel<<<dim3(8, 16), 256, SMEM_TOT>>>();

    heads1_kernel<<<(Bn * 128 + 255) / 256, 256>>>(Wa1, ba1, Wv1, bv1);
    heads2_kernel<<<(Bn + 255) / 256, 256>>>(Wa2, ba2, Wv2, bv2, out);
}

// round 10
// speedup vs baseline: 1.0428x; 1.0428x over previous
#include <cuda_runtime.h>
#include <cuda_bf16.h>
#include <math.h>
#include <stdint.h>

// Problem constants
#define Bn   1024
#define Tn   512
#define Dn   64
#define Hn   256
#define G4   1024
#define MIDn 64
#define An   3

// CTA = 128 rows x 64 gate-cols. K=320: x chunk (k 256..319) computed from a
// prefetched buffer before the h phase; h = 4 chunks k=64 (ch -> buf ch&1).
// A buffers: XOR-swizzled, pitch 128B. B resident: pitch 640B, XOR-swizzled.
#define ABUF   49152                    // per A buffer (3 planes x 128 rows x 128B)
#define NBUF   2
#define B_OFF  (NBUF*ABUF)              // 98304
#define BPITCH 640
#define SMEM_TOT (B_OFF + 3*64*BPITCH)  // 98304 + 122880 = 221184

// ---------------- device scratch (static, no allocation) ----------------
__device__ __nv_bfloat16 g_W[3][G4][320];          // [plane][gatecol][k] k0..255=h, 256..319=x
__device__ __nv_bfloat16 g_xT[3][Tn][Bn][Dn];      // split x, t-major
__device__ __nv_bfloat16 g_h[2][3][Bn][Hn];        // ping-pong split h
__device__ float g_br[G4];
__device__ float g_hfull[Bn*Hn];
__device__ float g_a1[Bn*MIDn];
__device__ float g_v1[Bn*MIDn];
__device__ int   g_bar4[32];                        // [bi][quarter] arrival counters

// ---------------- helpers ----------------
__device__ __forceinline__ void split3(float v, __nv_bfloat16& b1,
                                       __nv_bfloat16& b2, __nv_bfloat16& b3) {
    b1 = __float2bfloat16(v);
    float r = v - __bfloat162float(b1);
    b2 = __float2bfloat16(r);
    float r2 = r - __bfloat162float(b2);
    b3 = __float2bfloat16(r2);
}

__device__ __forceinline__ uint32_t smem_u32(const void* p) {
    uint32_t a;
    asm("{ .reg .u64 t; cvta.to.shared.u64 t, %1; cvt.u32.u64 %0, t; }" : "=r"(a) : "l"(p));
    return a;
}

__device__ __forceinline__ void cp16(uint32_t dst, const void* src) {
    asm volatile("cp.async.cg.shared.global [%0], [%1], 16;" :: "r"(dst), "l"(src) : "memory");
}
__device__ __forceinline__ void cp_commit() {
    asm volatile("cp.async.commit_group;" ::: "memory");
}

__device__ __forceinline__ int ld_acq(const int* p) {
    int v;
    asm volatile("ld.global.acquire.gpu.b32 %0, [%1];" : "=r"(v) : "l"(p) : "memory");
    return v;
}

#define LDSM4(R, addr) \
    asm volatile("ldmatrix.sync.aligned.m8n8.x4.shared.b16 {%0,%1,%2,%3}, [%4];" \
        : "=r"((R)[0]), "=r"((R)[1]), "=r"((R)[2]), "=r"((R)[3]) : "r"(addr))

__device__ __forceinline__ void mma_bf16(float c[4], const uint32_t a[4],
                                         uint32_t b0, uint32_t b1) {
    asm volatile(
        "mma.sync.aligned.m16n8k16.row.col.f32.bf16.bf16.f32 "
        "{%0,%1,%2,%3}, {%4,%5,%6,%7}, {%8,%9}, {%0,%1,%2,%3};"
        : "+f"(c[0]), "+f"(c[1]), "+f"(c[2]), "+f"(c[3])
        : "r"(a[0]), "r"(a[1]), "r"(a[2]), "r"(a[3]), "r"(b0), "r"(b1));
}

// ---------------- prep kernels ----------------
// k-space: k 0..255 = h units (Wc rows 64+k), k 256..319 = x dims (Wc rows k-256)
__global__ void wsplit_kernel(const float* __restrict__ Wc, const float* __restrict__ bc) {
    int idx = blockIdx.x * blockDim.x + threadIdx.x;
    if (idx < G4 * 320) {
        int k = idx % 320;
        int gcol = idx / 320;
        int u = gcol >> 2, g = gcol & 3;
        int r = (k < 256) ? (64 + k) : (k - 256);
        float w = Wc[r * G4 + g * Hn + u];
        __nv_bfloat16 s[3];
        split3(w, s[0], s[1], s[2]);
#pragma unroll
        for (int p = 0; p < 3; p++) g_W[p][gcol][k] = s[p];
    }
    if (idx < G4) {
        int u = idx >> 2, g = idx & 3;
        g_br[idx] = bc[g * Hn + u];
    }
}

__global__ void xsplit_kernel(const float* __restrict__ x) {
    int idx = blockIdx.x * blockDim.x + threadIdx.x;
    int d = idx & 63;
    int tt = (idx >> 6) & 511;
    int b = idx >> 15;
    if (b >= Bn) return;
    float v = x[((size_t)b * Tn + tt) * Dn + d];
    __nv_bfloat16 s[3];
    split3(v, s[0], s[1], s[2]);
#pragma unroll
    for (int p = 0; p < 3; p++) g_xT[p][tt][b][d] = s[p];
}

__global__ void init_kernel() {
    int idx = blockIdx.x * blockDim.x + threadIdx.x;
    if (idx < 3 * Bn * Hn / 2)
        ((unsigned*)g_h[0])[idx] = 0u;
    if (idx < 32) g_bar4[idx] = 0;
}

// ---------------- persistent step kernel ----------------
// grid (8, 16): bi = batch slice (128 rows), ci = 16 hidden units (64 gate cols)
__global__ __launch_bounds__(256)
void step_kernel() {
    extern __shared__ char dsm[];
    const uint32_t sbase = smem_u32(dsm);

    const int tid  = threadIdx.x;
    const int lane = tid & 31;
    const int warp = tid >> 5;
    const int wm = warp & 3;
    const int wn = warp >> 2;
    const int bi = blockIdx.x;
    const int ci = blockIdx.y;
    const int row0 = bi * 128;

    // resident B (weights, K=320): 3 planes x 64 cols x 640B, XOR-swizzled
#pragma unroll
    for (int i = 0; i < 30; i++) {
        int flat = i * 256 + tid;                 // < 7680
        int q = flat % 40;
        int n = (flat / 40) & 63;
        int p = flat / 2560;
        uint32_t off = (uint32_t)(q * 16) ^ (uint32_t)((n & 7) << 4);
        cp16(sbase + B_OFF + (uint32_t)(p * 64 + n) * BPITCH + off,
             (const char*)&g_W[p][ci * 64 + n][q * 8]);
    }
    cp_commit();

    float cold[8], nold[8];
#pragma unroll
    for (int q = 0; q < 8; q++) { cold[q] = 0.0f; nold[q] = 1.0f; }

    const int mrow = lane & 15;
    const int kAo  = (lane >> 4) << 3;
    const int nBo  = ((lane >> 4) << 3) + (lane & 7);
    const int kBo  = ((lane >> 3) & 1) << 3;
    const bool odd = lane & 1;
    const int jh = (lane >> 1) & 1;

    float cm[2][4][4], cl[2][4][4], cx[2][4][4];

    // one k=64 chunk: 4 k16 steps, 6-product bf16x6
    auto do_chunk = [&](uint32_t abase, uint32_t bko) {
#pragma unroll
        for (int ks = 0; ks < 4; ks++) {
            uint32_t a[3][2][4], b[3][2][4];
#pragma unroll
            for (int p = 0; p < 3; p++) {
#pragma unroll
                for (int mi = 0; mi < 2; mi++) {
                    int arow = wm * 32 + mi * 16 + mrow;
                    uint32_t off = (uint32_t)((ks * 16 + kAo) * 2) ^ (uint32_t)((arow & 7) << 4);
                    LDSM4(a[p][mi], abase + (uint32_t)(p * 128 + arow) * 128 + off);
                }
#pragma unroll
                for (int pr = 0; pr < 2; pr++) {
                    int brow = wn * 32 + pr * 16 + nBo;
                    uint32_t off = (bko + (uint32_t)((ks * 16 + kBo) * 2)) ^ (uint32_t)((brow & 7) << 4);
                    LDSM4(b[p][pr], sbase + B_OFF + (uint32_t)(p * 64 + brow) * BPITCH + off);
                }
            }
#pragma unroll
            for (int mi = 0; mi < 2; mi++)
#pragma unroll
                for (int ni = 0; ni < 4; ni++) {
                    const int pr = ni >> 1, o = (ni & 1) * 2;
                    mma_bf16(cm[mi][ni], a[0][mi], b[0][pr][o], b[0][pr][o+1]); // hi*hi
                    mma_bf16(cl[mi][ni], a[0][mi], b[1][pr][o], b[1][pr][o+1]); // hi*mid
                    mma_bf16(cl[mi][ni], a[1][mi], b[0][pr][o], b[0][pr][o+1]); // mid*hi
                    mma_bf16(cl[mi][ni], a[0][mi], b[2][pr][o], b[2][pr][o+1]); // hi*lo
                    mma_bf16(cl[mi][ni], a[1][mi], b[1][pr][o], b[1][pr][o+1]); // mid*mid
                    mma_bf16(cl[mi][ni], a[2][mi], b[0][pr][o], b[0][pr][o+1]); // lo*hi
                }
        }
    };

    // x(t) prefetch into buffer 1 (k 256..319)
    auto issue_x = [&](int t) {
#pragma unroll
        for (int i = 0; i < 12; i++) {
            int flat = i * 256 + tid;             // < 3072
            int q = flat & 7;
            int m = (flat >> 3) & 127;
            int p = flat >> 10;
            uint32_t off = (uint32_t)(q * 16) ^ (uint32_t)((m & 7) << 4);
            cp16(sbase + ABUF + (uint32_t)(p * 128 + m) * 128 + off,
                 (const char*)&g_xT[p][t][row0 + m][q * 8]);
        }
        cp_commit();
    };

    // h-chunk producer: chunk ch (k = ch*64..) -> buffer ch&1
    auto issue_h = [&](int ch, int hbuf) {
        const uint32_t abase = sbase + (uint32_t)(ch & 1) * ABUF;
#pragma unroll
        for (int i = 0; i < 12; i++) {
            int flat = i * 256 + tid;
            int q = flat & 7;
            int m = (flat >> 3) & 127;
            int p = flat >> 10;
            uint32_t off = (uint32_t)(q * 16) ^ (uint32_t)((m & 7) << 4);
            cp16(abase + (uint32_t)(p * 128 + m) * 128 + off,
                 (const char*)&g_h[hbuf][p][row0 + m][ch * 64 + q * 8]);
        }
        cp_commit();
    };

    // quarter barrier wait: h units [64q, 64q+64) of step t ready
    auto wait_q = [&](int q, int t) {
        const int tgt = 4 * t;
        const int* p = &g_bar4[bi * 4 + q];
        while (ld_acq(p) < tgt) { }
    };

    issue_x(0);

    for (int t = 0; t < Tn; t++) {
        const int hbuf = t & 1;

#pragma unroll
        for (int mi = 0; mi < 2; mi++)
#pragma unroll
            for (int ni = 0; ni < 4; ni++)
#pragma unroll
                for (int q = 0; q < 4; q++) { cm[mi][ni][q] = 0.0f; cl[mi][ni][q] = 0.0f; }

        // ---- x data (prefetched) ready; start h0 load, then compute x ----
        asm volatile("cp.async.wait_group 0;" ::: "memory");
        __syncthreads();

        wait_q(0, t);
        issue_h(0, hbuf);                          // -> buf0, flies during x compute

        do_chunk(sbase + ABUF, 512u);              // x part (k 256..319) from buf1

        // collapse x part + bias into cx, reset cm/cl
#pragma unroll
        for (int mi = 0; mi < 2; mi++)
#pragma unroll
            for (int ni = 0; ni < 4; ni++) {
                int col = ci * 64 + wn * 32 + ni * 8 + (lane & 3) * 2;
                float b0 = g_br[col], b1 = g_br[col + 1];
                cx[mi][ni][0] = cm[mi][ni][0] + cl[mi][ni][0] + b0;
                cx[mi][ni][1] = cm[mi][ni][1] + cl[mi][ni][1] + b1;
                cx[mi][ni][2] = cm[mi][ni][2] + cl[mi][ni][2] + b0;
                cx[mi][ni][3] = cm[mi][ni][3] + cl[mi][ni][3] + b1;
#pragma unroll
                for (int q = 0; q < 4; q++) { cm[mi][ni][q] = 0.0f; cl[mi][ni][q] = 0.0f; }
            }

        __syncthreads();                           // all warps done reading buf1 (x)
        wait_q(1, t);
        issue_h(1, hbuf);                          // -> buf1

        // ---- h phase: 4 chunks k=64, ping-pong buffers ----
#pragma unroll 1
        for (int ch = 0; ch < 4; ch++) {
            if (ch == 3) asm volatile("cp.async.wait_group 0;" ::: "memory");
            else         asm volatile("cp.async.wait_group 1;" ::: "memory");
            __syncthreads();

            do_chunk(sbase + (uint32_t)(ch & 1) * ABUF, (uint32_t)(ch * 128));

            __syncthreads();                       // chunk reads done
            if (ch + 2 < 4) {
                wait_q(ch + 2, t);
                issue_h(ch + 2, hbuf);             // refill buffer just consumed
            }
        }

        const bool last = (t == Tn - 1);
        if (!last) issue_x(t + 1);                 // -> buf1 (free); hides behind epilogue

        // ---- epilogue (Hs stages in buf0: last read was ch2, guarded by ch3 sync) ----
        __nv_bfloat16* Hs = (__nv_bfloat16*)dsm;   // [3][128][16]

#pragma unroll
        for (int mi = 0; mi < 2; mi++)
#pragma unroll
            for (int ni = 0; ni < 4; ni++) {
                float q0 = (cm[mi][ni][0] + cl[mi][ni][0]) + cx[mi][ni][0];
                float q1 = (cm[mi][ni][1] + cl[mi][ni][1]) + cx[mi][ni][1];
                float q2 = (cm[mi][ni][2] + cl[mi][ni][2]) + cx[mi][ni][2];
                float q3 = (cm[mi][ni][3] + cl[mi][ni][3]) + cx[mi][ni][3];
                float s0 = __shfl_xor_sync(0xFFFFFFFFu, q0, 1);
                float s1 = __shfl_xor_sync(0xFFFFFFFFu, q1, 1);
                float s2 = __shfl_xor_sync(0xFFFFFFFFu, q2, 1);
                float s3 = __shfl_xor_sync(0xFFFFFFFFu, q3, 1);

                float gi = odd ? s2 : q0;
                float gf = odd ? s3 : q1;
                float go = odd ? q2 : s0;
                float gz = odd ? q3 : s1;

                const int row = wm * 32 + mi * 16 + (lane >> 2) + (odd ? 8 : 0);
                const int ul  = wn * 8 + ni * 2 + jh;
                const int qi  = mi * 4 + ni;

                gi = fminf(fmaxf(gi, -5.0f), 5.0f);
                gf = fminf(fmaxf(gf, -5.0f), 5.0f);
                float iv = __expf(gi);
                float fv = __expf(gf);

                float cv = fv * cold[qi] + iv * (1.0f - 2.0f / (__expf(2.0f * gz) + 1.0f));
                cv = fminf(fmaxf(cv, -1e6f), 1e6f);
                float nv = fv * nold[qi] + iv;
                nv = fminf(fmaxf(nv, 1e-6f), 1e6f);
                cold[qi] = cv;
                nold[qi] = nv;

                float ov = 1.0f / (1.0f + __expf(-go));
                float hv = ov * (cv / nv);
                if (!isfinite(hv)) hv = 0.0f;

                __nv_bfloat16 h1, h2, h3;
                split3(hv, h1, h2, h3);
                Hs[(0 * 128 + row) * 16 + ul] = h1;
                Hs[(1 * 128 + row) * 16 + ul] = h2;
                Hs[(2 * 128 + row) * 16 + ul] = h3;
                if (last) g_hfull[(row0 + row) * Hn + ci * 16 + ul] = hv;
            }
        __syncthreads();

        if (!last) {
            const int nbuf = hbuf ^ 1;
#pragma unroll
            for (int i = 0; i < 3; i++) {
                int flat = i * 256 + tid;
                int q = flat & 1;
                int m = (flat >> 1) & 127;
                int p = flat >> 8;
                uint4 v = *(const uint4*)&Hs[(p * 128 + m) * 16 + q * 8];
                *(uint4*)&g_h[nbuf][p][row0 + m][ci * 16 + q * 8] = v;
            }
            __threadfence();
            __syncthreads();                       // Hs reads done; h visible
            if (tid == 0) atomicAdd(&g_bar4[bi * 4 + (ci >> 2)], 1);
        }
    }
}

// ---------------- heads ----------------
__global__ void heads1_kernel(const float* __restrict__ Wa1, const float* __restrict__ ba1,
                              const float* __restrict__ Wv1, const float* __restrict__ bv1) {
    int idx = blockIdx.x * blockDim.x + threadIdx.x;
    if (idx >= Bn * 128) return;
    int b = idx >> 7;
    int j = idx & 127;
    const float* hrow = g_hfull + b * Hn;
    if (j < MIDn) {
        float s = ba1[j];
#pragma unroll 8
        for (int k = 0; k < Hn; k++) s = fmaf(hrow[k], Wa1[k * MIDn + j], s);
        g_a1[b * MIDn + j] = fmaxf(s, 0.0f);
    } else {
        int jj = j - MIDn;
        float s = bv1[jj];
#pragma unroll 8
        for (int k = 0; k < Hn; k++) s = fmaf(hrow[k], Wv1[k * MIDn + jj], s);
        g_v1[b * MIDn + jj] = fmaxf(s, 0.0f);
    }
}

__global__ void heads2_kernel(const float* __restrict__ Wa2, const float* __restrict__ ba2,
                              const float* __restrict__ Wv2, const float* __restrict__ bv2,
                              float* __restrict__ out) {
    int b = blockIdx.x * blockDim.x + threadIdx.x;
    if (b >= Bn) return;
    float l0 = ba2[0], l1 = ba2[1], l2 = ba2[2];
#pragma unroll 8
    for (int m = 0; m < MIDn; m++) {
        float a = g_a1[b * MIDn + m];
        l0 = fmaf(a, Wa2[m * An + 0], l0);
        l1 = fmaf(a, Wa2[m * An + 1], l1);
        l2 = fmaf(a, Wa2[m * An + 2], l2);
    }
    float mx = fmaxf(l0, fmaxf(l1, l2));
    float e0 = expf(l0 - mx), e1 = expf(l1 - mx), e2 = expf(l2 - mx);
    float s = e0 + e1 + e2;
    out[b * An + 0] = e0 / s;
    out[b * An + 1] = e1 / s;
    out[b * An + 2] = e2 / s;

    float v = bv2[0];
#pragma unroll 8
    for (int m = 0; m < MIDn; m++) v = fmaf(g_v1[b * MIDn + m], Wv2[m], v);
    out[Bn * An + b] = v;
}

// ---------------- launch ----------------
extern "C" void kernel_launch(void* const* d_in, const int* in_sizes, int n_in,
                              void* d_out, int out_size) {
    const float* x   = (const float*)d_in[0];
    const float* Wc  = (const float*)d_in[1];
    const float* bc  = (const float*)d_in[2];
    const float* Wa1 = (const float*)d_in[3];
    const float* ba1 = (const float*)d_in[4];
    const float* Wa2 = (const float*)d_in[5];
    const float* ba2 = (const float*)d_in[6];
    const float* Wv1 = (const float*)d_in[7];
    const float* bv1 = (const float*)d_in[8];
    const float* Wv2 = (const float*)d_in[9];
    const float* bv2 = (const float*)d_in[10];
    float* out = (float*)d_out;

    cudaFuncSetAttribute(step_kernel, cudaFuncAttributeMaxDynamicSharedMemorySize, SMEM_TOT);

    wsplit_kernel<<<(G4 * 320 + 255) / 256, 256>>>(Wc, bc);
    xsplit_kernel<<<(Bn * Tn * Dn + 255) / 256, 256>>>(x);
    init_kernel<<<(3 * Bn * Hn / 2 + 255) / 256, 256>>>();

    step_kernel<<<dim3(8, 16), 256, SMEM_TOT>>>();

    heads1_kernel<<<(Bn * 128 + 255) / 256, 256>>>(Wa1, ba1, Wv1, bv1);
    heads2_kernel<<<(Bn + 255) / 256, 256>>>(Wa2, ba2, Wv2, bv2, out);
}

// round 11
// speedup vs baseline: 1.0526x; 1.0094x over previous
#include <cuda_runtime.h>
#include <cuda_bf16.h>
#include <math.h>
#include <stdint.h>

// Problem constants
#define Bn   1024
#define Tn   512
#define Dn   64
#define Hn   256
#define G4   1024
#define MIDn 64
#define An   3

// CTA = 128 rows x 64 gate-cols, 512 threads (16 warps, warp tile 32x16).
// K=320: x chunk (k 256..319) from a prefetched buffer; h = 4 chunks k=64.
#define ABUF   49152                    // per A buffer (3 planes x 128 rows x 128B)
#define NBUF   2
#define B_OFF  (NBUF*ABUF)              // 98304
#define BPITCH 640
#define SMEM_TOT (B_OFF + 3*64*BPITCH)  // 98304 + 122880 = 221184

// ---------------- device scratch (static, no allocation) ----------------
__device__ __nv_bfloat16 g_W[3][G4][320];          // [plane][gatecol][k] k0..255=h, 256..319=x
__device__ __nv_bfloat16 g_xT[3][Tn][Bn][Dn];      // split x, t-major
__device__ __nv_bfloat16 g_h[2][3][Bn][Hn];        // ping-pong split h
__device__ float g_br[G4];
__device__ float g_hfull[Bn*Hn];
__device__ float g_a1[Bn*MIDn];
__device__ float g_v1[Bn*MIDn];
__device__ int   g_bar4[32];                        // [bi][quarter] arrival counters

// ---------------- helpers ----------------
__device__ __forceinline__ void split3(float v, __nv_bfloat16& b1,
                                       __nv_bfloat16& b2, __nv_bfloat16& b3) {
    b1 = __float2bfloat16(v);
    float r = v - __bfloat162float(b1);
    b2 = __float2bfloat16(r);
    float r2 = r - __bfloat162float(b2);
    b3 = __float2bfloat16(r2);
}

__device__ __forceinline__ uint32_t smem_u32(const void* p) {
    uint32_t a;
    asm("{ .reg .u64 t; cvta.to.shared.u64 t, %1; cvt.u32.u64 %0, t; }" : "=r"(a) : "l"(p));
    return a;
}

__device__ __forceinline__ void cp16(uint32_t dst, const void* src) {
    asm volatile("cp.async.cg.shared.global [%0], [%1], 16;" :: "r"(dst), "l"(src) : "memory");
}
__device__ __forceinline__ void cp_commit() {
    asm volatile("cp.async.commit_group;" ::: "memory");
}

__device__ __forceinline__ int ld_acq(const int* p) {
    int v;
    asm volatile("ld.global.acquire.gpu.b32 %0, [%1];" : "=r"(v) : "l"(p) : "memory");
    return v;
}

#define LDSM4(R, addr) \
    asm volatile("ldmatrix.sync.aligned.m8n8.x4.shared.b16 {%0,%1,%2,%3}, [%4];" \
        : "=r"((R)[0]), "=r"((R)[1]), "=r"((R)[2]), "=r"((R)[3]) : "r"(addr))

__device__ __forceinline__ void mma_bf16(float c[4], const uint32_t a[4],
                                         uint32_t b0, uint32_t b1) {
    asm volatile(
        "mma.sync.aligned.m16n8k16.row.col.f32.bf16.bf16.f32 "
        "{%0,%1,%2,%3}, {%4,%5,%6,%7}, {%8,%9}, {%0,%1,%2,%3};"
        : "+f"(c[0]), "+f"(c[1]), "+f"(c[2]), "+f"(c[3])
        : "r"(a[0]), "r"(a[1]), "r"(a[2]), "r"(a[3]), "r"(b0), "r"(b1));
}

// ---------------- prep kernels ----------------
// k-space: k 0..255 = h units (Wc rows 64+k), k 256..319 = x dims (Wc rows k-256)
__global__ void wsplit_kernel(const float* __restrict__ Wc, const float* __restrict__ bc) {
    int idx = blockIdx.x * blockDim.x + threadIdx.x;
    if (idx < G4 * 320) {
        int k = idx % 320;
        int gcol = idx / 320;
        int u = gcol >> 2, g = gcol & 3;
        int r = (k < 256) ? (64 + k) : (k - 256);
        float w = Wc[r * G4 + g * Hn + u];
        __nv_bfloat16 s[3];
        split3(w, s[0], s[1], s[2]);
#pragma unroll
        for (int p = 0; p < 3; p++) g_W[p][gcol][k] = s[p];
    }
    if (idx < G4) {
        int u = idx >> 2, g = idx & 3;
        g_br[idx] = bc[g * Hn + u];
    }
}

__global__ void xsplit_kernel(const float* __restrict__ x) {
    int idx = blockIdx.x * blockDim.x + threadIdx.x;
    int d = idx & 63;
    int tt = (idx >> 6) & 511;
    int b = idx >> 15;
    if (b >= Bn) return;
    float v = x[((size_t)b * Tn + tt) * Dn + d];
    __nv_bfloat16 s[3];
    split3(v, s[0], s[1], s[2]);
#pragma unroll
    for (int p = 0; p < 3; p++) g_xT[p][tt][b][d] = s[p];
}

__global__ void init_kernel() {
    int idx = blockIdx.x * blockDim.x + threadIdx.x;
    if (idx < 3 * Bn * Hn / 2)
        ((unsigned*)g_h[0])[idx] = 0u;
    if (idx < 32) g_bar4[idx] = 0;
}

// ---------------- persistent step kernel ----------------
// grid (8, 16): bi = batch slice (128 rows), ci = 16 hidden units (64 gate cols)
// 512 threads, 16 warps: wm = warp&3 (m tile of 32), wn = warp>>2 (n tile of 16)
__global__ __launch_bounds__(512)
void step_kernel() {
    extern __shared__ char dsm[];
    const uint32_t sbase = smem_u32(dsm);

    const int tid  = threadIdx.x;
    const int lane = tid & 31;
    const int warp = tid >> 5;
    const int wm = warp & 3;
    const int wn = warp >> 2;
    const int bi = blockIdx.x;
    const int ci = blockIdx.y;
    const int row0 = bi * 128;

    // resident B (weights, K=320): 3 planes x 64 cols x 640B, XOR-swizzled
#pragma unroll
    for (int i = 0; i < 15; i++) {
        int flat = i * 512 + tid;                 // < 7680
        int q = flat % 40;
        int n = (flat / 40) & 63;
        int p = flat / 2560;
        uint32_t off = (uint32_t)(q * 16) ^ (uint32_t)((n & 7) << 4);
        cp16(sbase + B_OFF + (uint32_t)(p * 64 + n) * BPITCH + off,
             (const char*)&g_W[p][ci * 64 + n][q * 8]);
    }
    cp_commit();

    float cold[4], nold[4];
#pragma unroll
    for (int q = 0; q < 4; q++) { cold[q] = 0.0f; nold[q] = 1.0f; }

    const int mrow = lane & 15;
    const int kAo  = (lane >> 4) << 3;
    const int nBo  = ((lane >> 4) << 3) + (lane & 7);
    const int kBo  = ((lane >> 3) & 1) << 3;
    const bool odd = lane & 1;
    const int jh = (lane >> 1) & 1;

    float cm[2][2][4], cl[2][2][4], cx[2][2][4];

    // one k=64 chunk: 4 k16 steps, 6-product bf16x6, warp tile 32m x 16n
    auto do_chunk = [&](uint32_t abase, uint32_t bko) {
#pragma unroll
        for (int ks = 0; ks < 4; ks++) {
            uint32_t a[3][2][4], b[3][4];
#pragma unroll
            for (int p = 0; p < 3; p++) {
#pragma unroll
                for (int mi = 0; mi < 2; mi++) {
                    int arow = wm * 32 + mi * 16 + mrow;
                    uint32_t off = (uint32_t)((ks * 16 + kAo) * 2) ^ (uint32_t)((arow & 7) << 4);
                    LDSM4(a[p][mi], abase + (uint32_t)(p * 128 + arow) * 128 + off);
                }
                {
                    int brow = wn * 16 + nBo;
                    uint32_t off = (bko + (uint32_t)((ks * 16 + kBo) * 2)) ^ (uint32_t)((brow & 7) << 4);
                    LDSM4(b[p], sbase + B_OFF + (uint32_t)(p * 64 + brow) * BPITCH + off);
                }
            }
#pragma unroll
            for (int mi = 0; mi < 2; mi++)
#pragma unroll
                for (int ni = 0; ni < 2; ni++) {
                    const int o = ni * 2;
                    mma_bf16(cm[mi][ni], a[0][mi], b[0][o], b[0][o+1]); // hi*hi
                    mma_bf16(cl[mi][ni], a[0][mi], b[1][o], b[1][o+1]); // hi*mid
                    mma_bf16(cl[mi][ni], a[1][mi], b[0][o], b[0][o+1]); // mid*hi
                    mma_bf16(cl[mi][ni], a[0][mi], b[2][o], b[2][o+1]); // hi*lo
                    mma_bf16(cl[mi][ni], a[1][mi], b[1][o], b[1][o+1]); // mid*mid
                    mma_bf16(cl[mi][ni], a[2][mi], b[0][o], b[0][o+1]); // lo*hi
                }
        }
    };

    // x(t) prefetch into buffer 1 (k 256..319)
    auto issue_x = [&](int t) {
#pragma unroll
        for (int i = 0; i < 6; i++) {
            int flat = i * 512 + tid;             // < 3072
            int q = flat & 7;
            int m = (flat >> 3) & 127;
            int p = flat >> 10;
            uint32_t off = (uint32_t)(q * 16) ^ (uint32_t)((m & 7) << 4);
            cp16(sbase + ABUF + (uint32_t)(p * 128 + m) * 128 + off,
                 (const char*)&g_xT[p][t][row0 + m][q * 8]);
        }
        cp_commit();
    };

    // h-chunk producer: chunk ch (k = ch*64..) -> buffer ch&1
    auto issue_h = [&](int ch, int hbuf) {
        const uint32_t abase = sbase + (uint32_t)(ch & 1) * ABUF;
#pragma unroll
        for (int i = 0; i < 6; i++) {
            int flat = i * 512 + tid;
            int q = flat & 7;
            int m = (flat >> 3) & 127;
            int p = flat >> 10;
            uint32_t off = (uint32_t)(q * 16) ^ (uint32_t)((m & 7) << 4);
            cp16(abase + (uint32_t)(p * 128 + m) * 128 + off,
                 (const char*)&g_h[hbuf][p][row0 + m][ch * 64 + q * 8]);
        }
        cp_commit();
    };

    // quarter barrier wait: h units [64q, 64q+64) of step t ready
    auto wait_q = [&](int q, int t) {
        const int tgt = 4 * t;
        const int* p = &g_bar4[bi * 4 + q];
        while (ld_acq(p) < tgt) { }
    };

    issue_x(0);

    for (int t = 0; t < Tn; t++) {
        const int hbuf = t & 1;

#pragma unroll
        for (int mi = 0; mi < 2; mi++)
#pragma unroll
            for (int ni = 0; ni < 2; ni++)
#pragma unroll
                for (int q = 0; q < 4; q++) { cm[mi][ni][q] = 0.0f; cl[mi][ni][q] = 0.0f; }

        // ---- x data (prefetched) ready; start h0 load, then compute x ----
        asm volatile("cp.async.wait_group 0;" ::: "memory");
        __syncthreads();

        wait_q(0, t);
        issue_h(0, hbuf);                          // -> buf0, flies during x compute

        do_chunk(sbase + ABUF, 512u);              // x part (k 256..319) from buf1

        // collapse x part + bias into cx, reset cm/cl
#pragma unroll
        for (int mi = 0; mi < 2; mi++)
#pragma unroll
            for (int ni = 0; ni < 2; ni++) {
                int col = ci * 64 + wn * 16 + ni * 8 + (lane & 3) * 2;
                float b0 = g_br[col], b1 = g_br[col + 1];
                cx[mi][ni][0] = cm[mi][ni][0] + cl[mi][ni][0] + b0;
                cx[mi][ni][1] = cm[mi][ni][1] + cl[mi][ni][1] + b1;
                cx[mi][ni][2] = cm[mi][ni][2] + cl[mi][ni][2] + b0;
                cx[mi][ni][3] = cm[mi][ni][3] + cl[mi][ni][3] + b1;
#pragma unroll
                for (int q = 0; q < 4; q++) { cm[mi][ni][q] = 0.0f; cl[mi][ni][q] = 0.0f; }
            }

        __syncthreads();                           // all warps done reading buf1 (x)
        wait_q(1, t);
        issue_h(1, hbuf);                          // -> buf1

        // ---- h phase: 4 chunks k=64, ping-pong buffers ----
#pragma unroll 1
        for (int ch = 0; ch < 4; ch++) {
            if (ch == 3) asm volatile("cp.async.wait_group 0;" ::: "memory");
            else         asm volatile("cp.async.wait_group 1;" ::: "memory");
            __syncthreads();

            do_chunk(sbase + (uint32_t)(ch & 1) * ABUF, (uint32_t)(ch * 128));

            __syncthreads();                       // chunk reads done
            if (ch + 2 < 4) {
                wait_q(ch + 2, t);
                issue_h(ch + 2, hbuf);             // refill buffer just consumed
            }
        }

        const bool last = (t == Tn - 1);
        if (!last) issue_x(t + 1);                 // -> buf1 (free); hides behind epilogue

        // ---- epilogue (Hs stages in buf0; last buf0 read guarded by ch3 sync) ----
        __nv_bfloat16* Hs = (__nv_bfloat16*)dsm;   // [3][128][16]

#pragma unroll
        for (int mi = 0; mi < 2; mi++)
#pragma unroll
            for (int ni = 0; ni < 2; ni++) {
                float q0 = (cm[mi][ni][0] + cl[mi][ni][0]) + cx[mi][ni][0];
                float q1 = (cm[mi][ni][1] + cl[mi][ni][1]) + cx[mi][ni][1];
                float q2 = (cm[mi][ni][2] + cl[mi][ni][2]) + cx[mi][ni][2];
                float q3 = (cm[mi][ni][3] + cl[mi][ni][3]) + cx[mi][ni][3];
                float s0 = __shfl_xor_sync(0xFFFFFFFFu, q0, 1);
                float s1 = __shfl_xor_sync(0xFFFFFFFFu, q1, 1);
                float s2 = __shfl_xor_sync(0xFFFFFFFFu, q2, 1);
                float s3 = __shfl_xor_sync(0xFFFFFFFFu, q3, 1);

                float gi = odd ? s2 : q0;
                float gf = odd ? s3 : q1;
                float go = odd ? q2 : s0;
                float gz = odd ? q3 : s1;

                const int row = wm * 32 + mi * 16 + (lane >> 2) + (odd ? 8 : 0);
                const int ul  = wn * 4 + ni * 2 + jh;
                const int qi  = mi * 2 + ni;

                gi = fminf(fmaxf(gi, -5.0f), 5.0f);
                gf = fminf(fmaxf(gf, -5.0f), 5.0f);
                float iv = __expf(gi);
                float fv = __expf(gf);

                float cv = fv * cold[qi] + iv * (1.0f - 2.0f / (__expf(2.0f * gz) + 1.0f));
                cv = fminf(fmaxf(cv, -1e6f), 1e6f);
                float nv = fv * nold[qi] + iv;
                nv = fminf(fmaxf(nv, 1e-6f), 1e6f);
                cold[qi] = cv;
                nold[qi] = nv;

                float ov = 1.0f / (1.0f + __expf(-go));
                float hv = ov * (cv / nv);
                if (!isfinite(hv)) hv = 0.0f;

                __nv_bfloat16 h1, h2, h3;
                split3(hv, h1, h2, h3);
                Hs[(0 * 128 + row) * 16 + ul] = h1;
                Hs[(1 * 128 + row) * 16 + ul] = h2;
                Hs[(2 * 128 + row) * 16 + ul] = h3;
                if (last) g_hfull[(row0 + row) * Hn + ci * 16 + ul] = hv;
            }
        __syncthreads();

        if (!last) {
            const int nbuf = hbuf ^ 1;
#pragma unroll
            for (int i = 0; i < 2; i++) {
                int flat = i * 512 + tid;
                if (flat < 768) {
                    int q = flat & 1;
                    int m = (flat >> 1) & 127;
                    int p = flat >> 8;
                    uint4 v = *(const uint4*)&Hs[(p * 128 + m) * 16 + q * 8];
                    *(uint4*)&g_h[nbuf][p][row0 + m][ci * 16 + q * 8] = v;
                }
            }
            __threadfence();
            __syncthreads();                       // Hs reads done; h visible
            if (tid == 0) atomicAdd(&g_bar4[bi * 4 + (ci >> 2)], 1);
        }
    }
}

// ---------------- heads ----------------
__global__ void heads1_kernel(const float* __restrict__ Wa1, const float* __restrict__ ba1,
                              const float* __restrict__ Wv1, const float* __restrict__ bv1) {
    int idx = blockIdx.x * blockDim.x + threadIdx.x;
    if (idx >= Bn * 128) return;
    int b = idx >> 7;
    int j = idx & 127;
    const float* hrow = g_hfull + b * Hn;
    if (j < MIDn) {
        float s = ba1[j];
#pragma unroll 8
        for (int k = 0; k < Hn; k++) s = fmaf(hrow[k], Wa1[k * MIDn + j], s);
        g_a1[b * MIDn + j] = fmaxf(s, 0.0f);
    } else {
        int jj = j - MIDn;
        float s = bv1[jj];
#pragma unroll 8
        for (int k = 0; k < Hn; k++) s = fmaf(hrow[k], Wv1[k * MIDn + jj], s);
        g_v1[b * MIDn + jj] = fmaxf(s, 0.0f);
    }
}

__global__ void heads2_kernel(const float* __restrict__ Wa2, const float* __restrict__ ba2,
                              const float* __restrict__ Wv2, const float* __restrict__ bv2,
                              float* __restrict__ out) {
    int b = blockIdx.x * blockDim.x + threadIdx.x;
    if (b >= Bn) return;
    float l0 = ba2[0], l1 = ba2[1], l2 = ba2[2];
#pragma unroll 8
    for (int m = 0; m < MIDn; m++) {
        float a = g_a1[b * MIDn + m];
        l0 = fmaf(a, Wa2[m * An + 0], l0);
        l1 = fmaf(a, Wa2[m * An + 1], l1);
        l2 = fmaf(a, Wa2[m * An + 2], l2);
    }
    float mx = fmaxf(l0, fmaxf(l1, l2));
    float e0 = expf(l0 - mx), e1 = expf(l1 - mx), e2 = expf(l2 - mx);
    float s = e0 + e1 + e2;
    out[b * An + 0] = e0 / s;
    out[b * An + 1] = e1 / s;
    out[b * An + 2] = e2 / s;

    float v = bv2[0];
#pragma unroll 8
    for (int m = 0; m < MIDn; m++) v = fmaf(g_v1[b * MIDn + m], Wv2[m], v);
    out[Bn * An + b] = v;
}

// ---------------- launch ----------------
extern "C" void kernel_launch(void* const* d_in, const int* in_sizes, int n_in,
                              void* d_out, int out_size) {
    const float* x   = (const float*)d_in[0];
    const float* Wc  = (const float*)d_in[1];
    const float* bc  = (const float*)d_in[2];
    const float* Wa1 = (const float*)d_in[3];
    const float* ba1 = (const float*)d_in[4];
    const float* Wa2 = (const float*)d_in[5];
    const float* ba2 = (const float*)d_in[6];
    const float* Wv1 = (const float*)d_in[7];
    const float* bv1 = (const float*)d_in[8];
    const float* Wv2 = (const float*)d_in[9];
    const float* bv2 = (const float*)d_in[10];
    float* out = (float*)d_out;

    cudaFuncSetAttribute(step_kernel, cudaFuncAttributeMaxDynamicSharedMemorySize, SMEM_TOT);

    wsplit_kernel<<<(G4 * 320 + 255) / 256, 256>>>(Wc, bc);
    xsplit_kernel<<<(Bn * Tn * Dn + 255) / 256, 256>>>(x);
    init_kernel<<<(3 * Bn * Hn / 2 + 255) / 256, 256>>>();

    step_kernel<<<dim3(8, 16), 512, SMEM_TOT>>>();

    heads1_kernel<<<(Bn * 128 + 255) / 256, 256>>>(Wa1, ba1, Wv1, bv1);
    heads2_kernel<<<(Bn + 255) / 256, 256>>>(Wa2, ba2, Wv2, bv2, out);
}